// round 7
// baseline (speedup 1.0000x reference)
#include <cuda_runtime.h>
#include <math.h>
#include <stdint.h>

#define Bx 4
#define Dd 64
#define Nn 4096
#define Oo 128
#define Kk 16
#define NEG 0.01f
#define NEGINF (-1.0e30f)

// ------------------------- static device scratch ---------------------------
__device__ float g_S[(size_t)Bx * Nn * Nn];
__device__ float g_xx[Bx * Nn];
__device__ float g_ft[Bx * Nn * Dd];
__device__ float g_q[Bx * Dd * Nn];
__device__ float g_k[Bx * Dd * Nn];
__device__ float g_v[Bx * Dd * Nn];
__device__ float g_Aloc[(size_t)Bx * Nn * Oo];
__device__ float g_Bloc[(size_t)Bx * Nn * Oo];
__device__ int   g_idxb[Bx * Nn * Kk];
__device__ float g_ymax[(size_t)Bx * Nn * Oo];
__device__ float g_ymin[(size_t)Bx * Nn * Oo];
__device__ float g_z2[(size_t)Bx * Nn * Oo];
__device__ float g_z3[(size_t)Bx * Nn * Oo];
__device__ float g_fgt[Bx * Dd * Nn];
__device__ float g_rowmax[Bx * Nn];
__device__ float g_rowsum[Bx * Nn];
__device__ float g_p1s[512 * Oo], g_p1q[512 * Oo];
__device__ float g_p2s[256 * Oo], g_p2q[256 * Oo];
__device__ float g_p3s[1024 * Oo], g_p3q[1024 * Oo];
__device__ float g_sc1[Oo], g_sh1[Oo], g_sc2[Oo], g_sh2[Oo], g_sc3[Oo], g_sh3[Oo];

// ------------------------- helpers -----------------------------------------
__device__ __forceinline__ void tf32split_u(float x, uint32_t& hi, uint32_t& lo) {
    asm("cvt.rna.tf32.f32 %0, %1;" : "=r"(hi) : "f"(x));
    float l = x - __uint_as_float(hi);
    asm("cvt.rna.tf32.f32 %0, %1;" : "=r"(lo) : "f"(l));
}
__device__ __forceinline__ uint32_t tf32one(float x) {
    uint32_t h;
    asm("cvt.rna.tf32.f32 %0, %1;" : "=r"(h) : "f"(x));
    return h;
}
__device__ __forceinline__ void mma_m16n8k8(float* c, const uint32_t* a, const uint32_t* b) {
    asm volatile(
        "mma.sync.aligned.m16n8k8.row.col.f32.tf32.tf32.f32 "
        "{%0,%1,%2,%3}, {%4,%5,%6,%7}, {%8,%9}, {%0,%1,%2,%3};"
        : "+f"(c[0]), "+f"(c[1]), "+f"(c[2]), "+f"(c[3])
        : "r"(a[0]), "r"(a[1]), "r"(a[2]), "r"(a[3]), "r"(b[0]), "r"(b[1]));
}

// ------------------------- xx[b,n] = sum_d f^2 -----------------------------
__global__ void k_xx(const float* __restrict__ f) {
    int id = blockIdx.x * 256 + threadIdx.x;
    int b = id >> 12;
    int n = id & (Nn - 1);
    const float* fb = f + (size_t)b * Dd * Nn + n;
    float s = 0.f;
#pragma unroll
    for (int d = 0; d < Dd; d++) {
        float v = fb[(size_t)d * Nn];
        s = fmaf(v, v, s);
    }
    g_xx[id] = s;
}

// ------------------------- transpose f -> (B,N,D) --------------------------
__global__ __launch_bounds__(256) void k_tr(const float* __restrict__ f) {
    __shared__ float tile[32][33];
    int b = blockIdx.z, d0 = blockIdx.y * 32, n0 = blockIdx.x * 32;
    int tx = threadIdx.x & 31, ty = threadIdx.x >> 5;
#pragma unroll
    for (int i = 0; i < 4; i++)
        tile[ty + i * 8][tx] = f[((size_t)b * Dd + d0 + ty + i * 8) * Nn + n0 + tx];
    __syncthreads();
#pragma unroll
    for (int i = 0; i < 4; i++)
        g_ft[((size_t)b * Nn + n0 + ty + i * 8) * Dd + d0 + tx] = tile[tx][ty + i * 8];
}

// -------- warp-MMA tf32 GEMM: mode0 pd (3-term), mode1 qk/8 (1-term) -------
#define KST 136
__global__ __launch_bounds__(256, 2) void k_mm(const float* __restrict__ f, int mode) {
    extern __shared__ uint32_t dsm[];
    __shared__ float sXM[128], sXN[128];
    uint32_t* sAh = dsm;
    uint32_t* sAl = dsm + 32 * KST;
    uint32_t* sBh = dsm + 64 * KST;
    uint32_t* sBl = dsm + 96 * KST;
    int t = threadIdx.x, lane = t & 31, wid = t >> 5;
    int wm = wid & 3, wn = wid >> 2;
    int gid = lane >> 2, ctg = lane & 3;
    int b = blockIdx.z, m0 = blockIdx.y * 128, n0 = blockIdx.x * 128;
    const float* Ap = (mode ? g_q : f) + (size_t)b * Dd * Nn;
    const float* Bp = (mode ? g_k : f) + (size_t)b * Dd * Nn;
    if (mode == 0) {
        if (t < 128) sXM[t] = g_xx[b * Nn + m0 + t];
        else sXN[t - 128] = g_xx[b * Nn + n0 + t - 128];
    }
    float acc[2][8][4] = {};
    int nterm = (mode == 0) ? 3 : 1;
#pragma unroll
    for (int kc = 0; kc < 2; kc++) {
        int kc0 = kc * 32;
        __syncthreads();
#pragma unroll
        for (int i = 0; i < 16; i++) {
            int e = t + i * 256;
            int d = e >> 7, m = e & 127;
            float a  = Ap[(size_t)(kc0 + d) * Nn + m0 + m];
            float bb = Bp[(size_t)(kc0 + d) * Nn + n0 + m];
            if (mode == 0) {
                uint32_t hi, lo;
                tf32split_u(a, hi, lo);  sAh[d * KST + m] = hi; sAl[d * KST + m] = lo;
                tf32split_u(bb, hi, lo); sBh[d * KST + m] = hi; sBl[d * KST + m] = lo;
            } else {
                sAh[d * KST + m] = tf32one(a);
                sBh[d * KST + m] = tf32one(bb);
            }
        }
        __syncthreads();
#pragma unroll
        for (int ks = 0; ks < 4; ks++) {
            int kb = ks * 8 + ctg;
            uint32_t ah[2][4], al[2][4];
#pragma unroll
            for (int mi = 0; mi < 2; mi++) {
                int mb = wm * 32 + mi * 16 + gid;
                ah[mi][0] = sAh[kb * KST + mb];
                ah[mi][1] = sAh[kb * KST + mb + 8];
                ah[mi][2] = sAh[(kb + 4) * KST + mb];
                ah[mi][3] = sAh[(kb + 4) * KST + mb + 8];
                if (nterm == 3) {
                    al[mi][0] = sAl[kb * KST + mb];
                    al[mi][1] = sAl[kb * KST + mb + 8];
                    al[mi][2] = sAl[(kb + 4) * KST + mb];
                    al[mi][3] = sAl[(kb + 4) * KST + mb + 8];
                }
            }
#pragma unroll
            for (int nf = 0; nf < 8; nf++) {
                int nb = wn * 64 + nf * 8 + gid;
                uint32_t bh[2], bl[2];
                bh[0] = sBh[kb * KST + nb];
                bh[1] = sBh[(kb + 4) * KST + nb];
#pragma unroll
                for (int mi = 0; mi < 2; mi++)
                    mma_m16n8k8(acc[mi][nf], ah[mi], bh);
                if (nterm == 3) {
                    bl[0] = sBl[kb * KST + nb];
                    bl[1] = sBl[(kb + 4) * KST + nb];
#pragma unroll
                    for (int mi = 0; mi < 2; mi++) {
                        mma_m16n8k8(acc[mi][nf], ah[mi], bl);
                        mma_m16n8k8(acc[mi][nf], al[mi], bh);
                    }
                }
            }
        }
    }
    float* outp = g_S + (size_t)b * Nn * Nn;
#pragma unroll
    for (int mi = 0; mi < 2; mi++) {
#pragma unroll
        for (int nf = 0; nf < 8; nf++) {
            float* c = acc[mi][nf];
            int ml = wm * 32 + mi * 16 + gid;
            int nl = wn * 64 + nf * 8 + 2 * ctg;
            if (mode == 0) {
                float2 v0 = { 2.f * c[0] - sXM[ml] - sXN[nl],
                              2.f * c[1] - sXM[ml] - sXN[nl + 1] };
                float2 v1 = { 2.f * c[2] - sXM[ml + 8] - sXN[nl],
                              2.f * c[3] - sXM[ml + 8] - sXN[nl + 1] };
                *(float2*)&outp[(size_t)(m0 + ml) * Nn + n0 + nl] = v0;
                *(float2*)&outp[(size_t)(m0 + ml + 8) * Nn + n0 + nl] = v1;
            } else {
                float2 v0 = { c[0] * 0.125f, c[1] * 0.125f };
                float2 v1 = { c[2] * 0.125f, c[3] * 0.125f };
                *(float2*)&outp[(size_t)(m0 + ml) * Nn + n0 + nl] = v0;
                *(float2*)&outp[(size_t)(m0 + ml + 8) * Nn + n0 + nl] = v1;
            }
        }
    }
}

// -------------- top-16 per row via 4-pass radix select ---------------------
__global__ __launch_bounds__(256) void k_topk() {
    int row = blockIdx.x;
    int t = threadIdx.x;
    const float* r = g_S + (size_t)row * Nn;
    unsigned key[16];
#pragma unroll
    for (int i = 0; i < 16; i++) {
        unsigned u = __float_as_uint(r[t + i * 256]);
        key[i] = (u & 0x80000000u) ? ~u : (u | 0x80000000u);
    }
    __shared__ int hist[256];
    __shared__ int sufs[257];
    __shared__ unsigned sPrefix;
    __shared__ int sRemain;
    __shared__ int sOutc, sEqc;
    __shared__ int eqbuf[64];
    if (t == 0) { sRemain = Kk; sOutc = 0; sEqc = 0; }
    unsigned prefix = 0;
#pragma unroll
    for (int pass = 0; pass < 4; pass++) {
        int shift = 24 - 8 * pass;
        hist[t] = 0;
        __syncthreads();
#pragma unroll
        for (int i = 0; i < 16; i++) {
            bool act = (pass == 0) || ((key[i] >> (shift + 8)) == prefix);
            if (act) atomicAdd(&hist[(key[i] >> shift) & 255], 1);
        }
        __syncthreads();
        sufs[t] = hist[t];
        if (t == 0) sufs[256] = 0;
        __syncthreads();
#pragma unroll
        for (int off = 1; off < 256; off <<= 1) {
            int add = (t + off < 256) ? sufs[t + off] : 0;
            __syncthreads();
            sufs[t] += add;
            __syncthreads();
        }
        int remain = sRemain;
        if (sufs[t] >= remain && sufs[t + 1] < remain) {
            sPrefix = (prefix << 8) | (unsigned)t;
            sRemain = remain - sufs[t + 1];
        }
        __syncthreads();
        prefix = sPrefix;
    }
    unsigned T = prefix;
    int remain = sRemain;
    int* outp = g_idxb + (size_t)row * Kk;
#pragma unroll
    for (int i = 0; i < 16; i++) {
        int idx = t + i * 256;
        if (key[i] > T) {
            int p = atomicAdd(&sOutc, 1);
            outp[p] = idx;
        } else if (key[i] == T) {
            int e = atomicAdd(&sEqc, 1);
            if (e < 64) eqbuf[e] = idx;
        }
    }
    __syncthreads();
    if (t == 0) {
        int base = sOutc;
        int ec = sEqc < 64 ? sEqc : 64;
        for (int rnd = 0; rnd < remain; rnd++) {
            int bi = 1 << 30, bp = -1;
            for (int e = 0; e < ec; e++)
                if (eqbuf[e] < bi) { bi = eqbuf[e]; bp = e; }
            outp[base + rnd] = bi;
            eqbuf[bp] = 1 << 30;
        }
    }
}

// -------- A = W[:, :64] . x, Bv = W[:, 64:128] . x  ------------------------
__global__ __launch_bounds__(256) void k_projAB(const float* __restrict__ wl) {
    __shared__ float sF[64][64];
    int bn0 = blockIdx.x * 64;
    int t = threadIdx.x;
    for (int e = t; e < 4096; e += 256) {
        int n = e >> 6, d = e & 63;
        sF[n][d] = g_ft[(size_t)(bn0 + n) * Dd + d];
    }
    __syncthreads();
    int half = t >> 7, o = t & 127;
    float wr[64];
#pragma unroll
    for (int d = 0; d < 64; d++) wr[d] = wl[o * 129 + half * 64 + d];
    float* dst = half ? g_Bloc : g_Aloc;
    for (int nn = 0; nn < 64; nn++) {
        float acc = 0.f;
#pragma unroll
        for (int d = 0; d < 64; d++) acc = fmaf(wr[d], sF[nn][d], acc);
        dst[(size_t)(bn0 + nn) * Oo + o] = acc;
    }
}

// --- gather neighbors, dist, y = A + Bv[j] + w_last*dist; max/min + stats --
__global__ __launch_bounds__(128) void k_intra(const float* __restrict__ wl) {
    __shared__ float sCen[64];
    __shared__ float sPart[16][8];
    __shared__ float sDist[16];
    __shared__ int sJ[16];
    int t = threadIdx.x;
    float wlast = wl[t * 129 + 128];
    float accS = 0.f, accQ = 0.f;
    for (int g = 0; g < 32; g++) {
        int bn = blockIdx.x * 32 + g;
        int b = bn >> 12;
        if (t < 64) sCen[t] = g_ft[(size_t)bn * Dd + t];
        __syncthreads();
        {
            int k = t >> 3, dg = t & 7;
            int j = g_idxb[(size_t)bn * Kk + k];
            const float* nr = g_ft + ((size_t)b * Nn + j) * Dd + dg * 8;
            float p = 0.f;
#pragma unroll
            for (int d = 0; d < 8; d++) {
                float df = nr[d] - sCen[dg * 8 + d];
                p = fmaf(df, df, p);
            }
            sPart[k][dg] = p;
            if (dg == 0) sJ[k] = j;
        }
        __syncthreads();
        if (t < 16) {
            float s = 0.f;
#pragma unroll
            for (int d = 0; d < 8; d++) s += sPart[t][d];
            sDist[t] = sqrtf(s);
        }
        __syncthreads();
        float a = g_Aloc[(size_t)bn * Oo + t];
        float mx = NEGINF, mn = -NEGINF;
#pragma unroll
        for (int kk = 0; kk < Kk; kk++) {
            int jj = sJ[kk];
            float y = a + g_Bloc[((size_t)b * Nn + jj) * Oo + t] + wlast * sDist[kk];
            mx = fmaxf(mx, y);
            mn = fminf(mn, y);
            accS += y;
            accQ = fmaf(y, y, accQ);
        }
        g_ymax[(size_t)bn * Oo + t] = mx;
        g_ymin[(size_t)bn * Oo + t] = mn;
        __syncthreads();
    }
    g_p1s[(size_t)blockIdx.x * Oo + t] = accS;
    g_p1q[(size_t)blockIdx.x * Oo + t] = accQ;
}

// ------------------------- q,k,v projections -------------------------------
__global__ __launch_bounds__(192) void k_qkv(const float* __restrict__ f,
    const float* __restrict__ wq, const float* __restrict__ bq,
    const float* __restrict__ wk, const float* __restrict__ bk,
    const float* __restrict__ wv, const float* __restrict__ bv) {
    __shared__ float sF[64][64];
    int b = blockIdx.y, n0 = blockIdx.x * 64, t = threadIdx.x;
    const float* fb = f + (size_t)b * Dd * Nn;
    for (int e = t; e < 4096; e += 192) {
        int d = e >> 6, nn = e & 63;
        sF[d][nn] = fb[(size_t)d * Nn + n0 + nn];
    }
    __syncthreads();
    int grp = t / 64, o = t % 64;
    const float* W = grp == 0 ? wq : (grp == 1 ? wk : wv);
    const float* bias = grp == 0 ? bq : (grp == 1 ? bk : bv);
    float* outp = (grp == 0 ? g_q : (grp == 1 ? g_k : g_v)) + ((size_t)b * Dd + o) * Nn + n0;
    float wr[64];
#pragma unroll
    for (int d = 0; d < 64; d++) wr[d] = W[o * 64 + d];
    for (int nn = 0; nn < 64; nn++) {
        float acc = bias[o];
#pragma unroll
        for (int d = 0; d < 64; d++) acc = fmaf(wr[d], sF[d][nn], acc);
        outp[nn] = acc;
    }
}

// ------------------- per-row online max & sum(exp) -------------------------
__global__ __launch_bounds__(128) void k_rowstats() {
    int row = blockIdx.x;
    int t = threadIdx.x;
    const float* r = g_S + (size_t)row * Nn;
    float m = NEGINF, s = 0.f;
#pragma unroll 4
    for (int i = 0; i < 32; i++) {
        float v = r[t + i * 128];
        if (v > m) { s = s * __expf(m - v) + 1.0f; m = v; }
        else s += __expf(v - m);
    }
#pragma unroll
    for (int off = 16; off; off >>= 1) {
        float om = __shfl_down_sync(0xffffffffu, m, off);
        float os = __shfl_down_sync(0xffffffffu, s, off);
        if (om > m) { s = s * __expf(m - om) + os; m = om; }
        else s += os * __expf(om - m);
    }
    __shared__ float sm[4], ss[4];
    int lane = t & 31, wid = t >> 5;
    if (lane == 0) { sm[wid] = m; ss[wid] = s; }
    __syncthreads();
    if (t == 0) {
        float M = sm[0], S = ss[0];
#pragma unroll
        for (int w = 1; w < 4; w++) {
            if (sm[w] > M) { S = S * __expf(M - sm[w]) + ss[w]; M = sm[w]; }
            else S += ss[w] * __expf(sm[w] - M);
        }
        g_rowmax[row] = M;
        g_rowsum[row] = S;
    }
}

// ------ fgt = softmax(S) @ V via warp-MMA tf32 (single-term) ---------------
// CTA: 128 m-rows x all 64 d. 8 warps, each 16 m-rows.
// sP[m=128][k=64 pad 72], sV[d=64][k=64 pad 72].
__global__ __launch_bounds__(256, 2) void k_PV() {
    extern __shared__ uint32_t pvs[];
    uint32_t* sP = pvs;                  // 128*72
    uint32_t* sV = pvs + 128 * 72;       // 64*72
    __shared__ float sRM[128], sIS[128];
    int t = threadIdx.x, lane = t & 31, wid = t >> 5;
    int gid = lane >> 2, ctg = lane & 3;
    int b = blockIdx.y, m0 = blockIdx.x * 128;
    if (t < 128) {
        sRM[t] = g_rowmax[(size_t)b * Nn + m0 + t];
        sIS[t] = 1.0f / g_rowsum[(size_t)b * Nn + m0 + t];
    }
    const float* Sb = g_S + ((size_t)b * Nn + m0) * Nn;
    const float* vb = g_v + (size_t)b * Dd * Nn;
    int mwb = wid * 16;
    float acc[8][4] = {};
    for (int nc = 0; nc < 64; nc++) {
        int n0 = nc * 64;
        __syncthreads();
#pragma unroll
        for (int i = 0; i < 32; i++) {
            int e = t + i * 256;
            int mi = e >> 6, ni = e & 63;
            float s = Sb[(size_t)mi * Nn + n0 + ni];
            sP[mi * 72 + ni] = tf32one(__expf(s - sRM[mi]));
        }
#pragma unroll
        for (int i = 0; i < 16; i++) {
            int e = t + i * 256;
            int di = e >> 6, ni = e & 63;
            sV[di * 72 + ni] = tf32one(vb[(size_t)di * Nn + n0 + ni]);
        }
        __syncthreads();
#pragma unroll
        for (int ks = 0; ks < 8; ks++) {
            int kb = ks * 8 + ctg;
            uint32_t a[4];
            a[0] = sP[(mwb + gid) * 72 + kb];
            a[1] = sP[(mwb + gid + 8) * 72 + kb];
            a[2] = sP[(mwb + gid) * 72 + kb + 4];
            a[3] = sP[(mwb + gid + 8) * 72 + kb + 4];
#pragma unroll
            for (int nf = 0; nf < 8; nf++) {
                int nb = nf * 8 + gid;
                uint32_t bb[2];
                bb[0] = sV[nb * 72 + kb];
                bb[1] = sV[nb * 72 + kb + 4];
                mma_m16n8k8(acc[nf], a, bb);
            }
        }
    }
    float is0 = sIS[mwb + gid], is8 = sIS[mwb + gid + 8];
    int m_ = m0 + mwb + gid;
#pragma unroll
    for (int nf = 0; nf < 8; nf++) {
        int d0 = nf * 8 + 2 * ctg;
        g_fgt[((size_t)b * Dd + d0) * Nn + m_]         = acc[nf][0] * is0;
        g_fgt[((size_t)b * Dd + d0 + 1) * Nn + m_]     = acc[nf][1] * is0;
        g_fgt[((size_t)b * Dd + d0) * Nn + m_ + 8]     = acc[nf][2] * is8;
        g_fgt[((size_t)b * Dd + d0 + 1) * Nn + m_ + 8] = acc[nf][3] * is8;
    }
}

// ------------------- inter pre-bn: z2 = w_sem . fgt ------------------------
__global__ __launch_bounds__(128) void k_inter(const float* __restrict__ wsem) {
    __shared__ float sF[64][64];
    int b = blockIdx.y, n0 = blockIdx.x * 64, t = threadIdx.x;
    const float* fb = g_fgt + (size_t)b * Dd * Nn;
    for (int e = t; e < 4096; e += 128) {
        int d = e >> 6, nn = e & 63;
        sF[d][nn] = fb[(size_t)d * Nn + n0 + nn];
    }
    __syncthreads();
    float wr[64];
#pragma unroll
    for (int d = 0; d < 64; d++) wr[d] = wsem[t * 64 + d];
    float aS = 0.f, aQ = 0.f;
    for (int nn = 0; nn < 64; nn++) {
        float acc = 0.f;
#pragma unroll
        for (int d = 0; d < 64; d++) acc = fmaf(wr[d], sF[d][nn], acc);
        g_z2[((size_t)b * Nn + n0 + nn) * Oo + t] = acc;
        aS += acc;
        aQ = fmaf(acc, acc, aQ);
    }
    int blk = blockIdx.y * gridDim.x + blockIdx.x;
    g_p2s[(size_t)blk * Oo + t] = aS;
    g_p2q[(size_t)blk * Oo + t] = aQ;
}

// --------- bn stat finalize ------------------------------------------------
__global__ void k_bnstats(int which, int nblk, float invcnt,
                          const float* __restrict__ gamma, const float* __restrict__ beta) {
    int o = threadIdx.x;
    const float *ps, *pq;
    float *sc, *sh;
    if (which == 1) { ps = g_p1s; pq = g_p1q; sc = g_sc1; sh = g_sh1; }
    else if (which == 2) { ps = g_p2s; pq = g_p2q; sc = g_sc2; sh = g_sh2; }
    else { ps = g_p3s; pq = g_p3q; sc = g_sc3; sh = g_sh3; }
    float s = 0.f, q = 0.f;
    for (int i = 0; i < nblk; i++) {
        s += ps[(size_t)i * Oo + o];
        q += pq[(size_t)i * Oo + o];
    }
    float mean = s * invcnt;
    float var = q * invcnt - mean * mean;
    float scl = gamma[o] / sqrtf(var + 1e-5f);
    sc[o] = scl;
    sh[o] = beta[o] - mean * scl;
}

// --------- z3 = w_full . [lrelu(bn1(intra)); lrelu(bn2(inter))] ------------
__global__ __launch_bounds__(128) void k_z3(const float* __restrict__ wfull) {
    __shared__ float sC[16][256];
    __shared__ float sW[32][129];
    int bn0 = blockIdx.x * 16, t = threadIdx.x;
    for (int e = t; e < 16 * 256; e += 128) {
        int n = e >> 8, c = e & 255;
        int bn = bn0 + n;
        float pre;
        if (c < 128) {
            float s1 = g_sc1[c];
            float ym = (s1 >= 0.f) ? g_ymax[(size_t)bn * Oo + c] : g_ymin[(size_t)bn * Oo + c];
            pre = fmaf(s1, ym, g_sh1[c]);
        } else {
            int o = c - 128;
            pre = fmaf(g_sc2[o], g_z2[(size_t)bn * Oo + o], g_sh2[o]);
        }
        sC[n][c] = pre >= 0.f ? pre : NEG * pre;
    }
    float acc[16] = {};
    for (int ch = 0; ch < 8; ch++) {
        __syncthreads();
        for (int e = t; e < 32 * 128; e += 128) {
            int o = e >> 5, c = e & 31;
            sW[c][o] = wfull[(size_t)o * 256 + ch * 32 + c];
        }
        __syncthreads();
#pragma unroll 4
        for (int c = 0; c < 32; c++) {
            float w = sW[c][t];
            int cg = ch * 32 + c;
#pragma unroll
            for (int n = 0; n < 16; n++) acc[n] = fmaf(w, sC[n][cg], acc[n]);
        }
    }
    float aS = 0.f, aQ = 0.f;
#pragma unroll
    for (int n = 0; n < 16; n++) {
        float z = acc[n];
        g_z3[(size_t)(bn0 + n) * Oo + t] = z;
        aS += z;
        aQ = fmaf(z, z, aQ);
    }
    g_p3s[(size_t)blockIdx.x * Oo + t] = aS;
    g_p3q[(size_t)blockIdx.x * Oo + t] = aQ;
}

// --------- out[b,o,n] = lrelu(bn3(z3)) with transpose ----------------------
__global__ __launch_bounds__(256) void k_out(float* __restrict__ out) {
    __shared__ float tile[32][33];
    int b = blockIdx.z, o0 = blockIdx.y * 32, n0 = blockIdx.x * 32;
    int tx = threadIdx.x & 31, ty = threadIdx.x >> 5;
    float scl = g_sc3[o0 + tx], sh = g_sh3[o0 + tx];
#pragma unroll
    for (int i = 0; i < 4; i++) {
        int n = n0 + ty + i * 8;
        float v = fmaf(scl, g_z3[((size_t)b * Nn + n) * Oo + o0 + tx], sh);
        tile[ty + i * 8][tx] = v >= 0.f ? v : NEG * v;
    }
    __syncthreads();
#pragma unroll
    for (int i = 0; i < 4; i++) {
        int o = o0 + ty + i * 8;
        out[((size_t)b * Oo + o) * Nn + n0 + tx] = tile[tx][ty + i * 8];
    }
}

// ---------------------------------------------------------------------------
extern "C" void kernel_launch(void* const* d_in, const int* in_sizes, int n_in,
                              void* d_out, int out_size) {
    const float* f       = (const float*)d_in[0];
    const float* w_local = (const float*)d_in[1];
    const float* g_local = (const float*)d_in[2];
    const float* b_local = (const float*)d_in[3];
    const float* w_sem   = (const float*)d_in[4];
    const float* g_sem   = (const float*)d_in[5];
    const float* b_sem   = (const float*)d_in[6];
    const float* w_full  = (const float*)d_in[7];
    const float* g_full  = (const float*)d_in[8];
    const float* b_full  = (const float*)d_in[9];
    const float* wq = (const float*)d_in[10];
    const float* bq = (const float*)d_in[11];
    const float* wk = (const float*)d_in[12];
    const float* bk = (const float*)d_in[13];
    const float* wv = (const float*)d_in[14];
    const float* bv = (const float*)d_in[15];
    float* out = (float*)d_out;

    const int MM_SMEM = 128 * KST * 4;          // 69632 bytes
    const int PV_SMEM = (128 + 64) * 72 * 4;    // 55296 bytes
    cudaFuncSetAttribute(k_mm, cudaFuncAttributeMaxDynamicSharedMemorySize, MM_SMEM);
    cudaFuncSetAttribute(k_PV, cudaFuncAttributeMaxDynamicSharedMemorySize, PV_SMEM);

    k_xx<<<64, 256>>>(f);
    k_tr<<<dim3(Nn / 32, Dd / 32, Bx), 256>>>(f);
    k_mm<<<dim3(32, 32, Bx), 256, MM_SMEM>>>(f, 0);
    k_topk<<<Bx * Nn, 256>>>();
    k_projAB<<<Bx * Nn / 64, 256>>>(w_local);
    k_intra<<<Bx * Nn / 32, 128>>>(w_local);
    k_bnstats<<<1, 128>>>(1, 512, 1.0f / (Bx * Nn * Kk), g_local, b_local);
    k_qkv<<<dim3(64, Bx), 192>>>(f, wq, bq, wk, bk, wv, bv);
    k_mm<<<dim3(32, 32, Bx), 256, MM_SMEM>>>(f, 1);
    k_rowstats<<<Bx * Nn, 128>>>();
    k_PV<<<dim3(32, Bx), 256, PV_SMEM>>>();
    k_inter<<<dim3(64, Bx), 128>>>(w_sem);
    k_bnstats<<<1, 128>>>(2, 256, 1.0f / (Bx * Nn), g_sem, b_sem);
    k_z3<<<Bx * Nn / 16, 128>>>(w_full);
    k_bnstats<<<1, 128>>>(3, 1024, 1.0f / (Bx * Nn), g_full, b_full);
    k_out<<<dim3(Nn / 32, Oo / 32, Bx), 256>>>(out);
}

// round 8
// speedup vs baseline: 1.4551x; 1.4551x over previous
#include <cuda_runtime.h>
#include <math.h>
#include <stdint.h>

#define Bx 4
#define Dd 64
#define Nn 4096
#define Oo 128
#define Kk 16
#define NEG 0.01f
#define NEGINF (-1.0e30f)

// ------------------------- static device scratch ---------------------------
__device__ float g_S[(size_t)Bx * Nn * Nn];
__device__ float g_xx[Bx * Nn];
__device__ float g_ft[Bx * Nn * Dd];
__device__ float g_q[Bx * Dd * Nn];
__device__ float g_k[Bx * Dd * Nn];
__device__ float g_v[Bx * Dd * Nn];
__device__ float g_Aloc[(size_t)Bx * Nn * Oo];
__device__ float g_Bloc[(size_t)Bx * Nn * Oo];
__device__ int   g_idxb[Bx * Nn * Kk];
__device__ float g_ymax[(size_t)Bx * Nn * Oo];
__device__ float g_ymin[(size_t)Bx * Nn * Oo];
__device__ float g_z2[(size_t)Bx * Nn * Oo];
__device__ float g_z3[(size_t)Bx * Nn * Oo];
__device__ float g_fgt[Bx * Dd * Nn];
__device__ float g_p1s[512 * Oo], g_p1q[512 * Oo];
__device__ float g_p2s[256 * Oo], g_p2q[256 * Oo];
__device__ float g_p3s[1024 * Oo], g_p3q[1024 * Oo];
__device__ float g_sc1[Oo], g_sh1[Oo], g_sc2[Oo], g_sh2[Oo], g_sc3[Oo], g_sh3[Oo];

// ------------------------- helpers -----------------------------------------
__device__ __forceinline__ void tf32split_u(float x, uint32_t& hi, uint32_t& lo) {
    asm("cvt.rna.tf32.f32 %0, %1;" : "=r"(hi) : "f"(x));
    float l = x - __uint_as_float(hi);
    asm("cvt.rna.tf32.f32 %0, %1;" : "=r"(lo) : "f"(l));
}
__device__ __forceinline__ uint32_t tf32one(float x) {
    uint32_t h;
    asm("cvt.rna.tf32.f32 %0, %1;" : "=r"(h) : "f"(x));
    return h;
}
__device__ __forceinline__ void mma_m16n8k8(float* c, const uint32_t* a, const uint32_t* b) {
    asm volatile(
        "mma.sync.aligned.m16n8k8.row.col.f32.tf32.tf32.f32 "
        "{%0,%1,%2,%3}, {%4,%5,%6,%7}, {%8,%9}, {%0,%1,%2,%3};"
        : "+f"(c[0]), "+f"(c[1]), "+f"(c[2]), "+f"(c[3])
        : "r"(a[0]), "r"(a[1]), "r"(a[2]), "r"(a[3]), "r"(b[0]), "r"(b[1]));
}

// ------------------------- xx[b,n] = sum_d f^2 -----------------------------
__global__ void k_xx(const float* __restrict__ f) {
    int id = blockIdx.x * 256 + threadIdx.x;
    int b = id >> 12;
    int n = id & (Nn - 1);
    const float* fb = f + (size_t)b * Dd * Nn + n;
    float s = 0.f;
#pragma unroll
    for (int d = 0; d < Dd; d++) {
        float v = fb[(size_t)d * Nn];
        s = fmaf(v, v, s);
    }
    g_xx[id] = s;
}

// ------------------------- transpose f -> (B,N,D) --------------------------
__global__ __launch_bounds__(256) void k_tr(const float* __restrict__ f) {
    __shared__ float tile[32][33];
    int b = blockIdx.z, d0 = blockIdx.y * 32, n0 = blockIdx.x * 32;
    int tx = threadIdx.x & 31, ty = threadIdx.x >> 5;
#pragma unroll
    for (int i = 0; i < 4; i++)
        tile[ty + i * 8][tx] = f[((size_t)b * Dd + d0 + ty + i * 8) * Nn + n0 + tx];
    __syncthreads();
#pragma unroll
    for (int i = 0; i < 4; i++)
        g_ft[((size_t)b * Nn + n0 + ty + i * 8) * Dd + d0 + tx] = tile[tx][ty + i * 8];
}

// -------- warp-MMA tf32 GEMM: pd (3-term split) -> g_S ---------------------
#define KST 136
__global__ __launch_bounds__(256, 2) void k_mm(const float* __restrict__ f) {
    extern __shared__ uint32_t dsm[];
    __shared__ float sXM[128], sXN[128];
    uint32_t* sAh = dsm;
    uint32_t* sAl = dsm + 32 * KST;
    uint32_t* sBh = dsm + 64 * KST;
    uint32_t* sBl = dsm + 96 * KST;
    int t = threadIdx.x, lane = t & 31, wid = t >> 5;
    int wm = wid & 3, wn = wid >> 2;
    int gid = lane >> 2, ctg = lane & 3;
    int b = blockIdx.z, m0 = blockIdx.y * 128, n0 = blockIdx.x * 128;
    const float* Ap = f + (size_t)b * Dd * Nn;
    if (t < 128) sXM[t] = g_xx[b * Nn + m0 + t];
    else sXN[t - 128] = g_xx[b * Nn + n0 + t - 128];
    float acc[2][8][4] = {};
#pragma unroll
    for (int kc = 0; kc < 2; kc++) {
        int kc0 = kc * 32;
        __syncthreads();
#pragma unroll
        for (int i = 0; i < 16; i++) {
            int e = t + i * 256;
            int d = e >> 7, m = e & 127;
            float a  = Ap[(size_t)(kc0 + d) * Nn + m0 + m];
            float bb = Ap[(size_t)(kc0 + d) * Nn + n0 + m];
            uint32_t hi, lo;
            tf32split_u(a, hi, lo);  sAh[d * KST + m] = hi; sAl[d * KST + m] = lo;
            tf32split_u(bb, hi, lo); sBh[d * KST + m] = hi; sBl[d * KST + m] = lo;
        }
        __syncthreads();
#pragma unroll
        for (int ks = 0; ks < 4; ks++) {
            int kb = ks * 8 + ctg;
            uint32_t ah[2][4], al[2][4];
#pragma unroll
            for (int mi = 0; mi < 2; mi++) {
                int mb = wm * 32 + mi * 16 + gid;
                ah[mi][0] = sAh[kb * KST + mb];
                ah[mi][1] = sAh[kb * KST + mb + 8];
                ah[mi][2] = sAh[(kb + 4) * KST + mb];
                ah[mi][3] = sAh[(kb + 4) * KST + mb + 8];
                al[mi][0] = sAl[kb * KST + mb];
                al[mi][1] = sAl[kb * KST + mb + 8];
                al[mi][2] = sAl[(kb + 4) * KST + mb];
                al[mi][3] = sAl[(kb + 4) * KST + mb + 8];
            }
#pragma unroll
            for (int nf = 0; nf < 8; nf++) {
                int nb = wn * 64 + nf * 8 + gid;
                uint32_t bh[2], bl[2];
                bh[0] = sBh[kb * KST + nb];
                bh[1] = sBh[(kb + 4) * KST + nb];
                bl[0] = sBl[kb * KST + nb];
                bl[1] = sBl[(kb + 4) * KST + nb];
#pragma unroll
                for (int mi = 0; mi < 2; mi++) {
                    mma_m16n8k8(acc[mi][nf], ah[mi], bh);
                    mma_m16n8k8(acc[mi][nf], ah[mi], bl);
                    mma_m16n8k8(acc[mi][nf], al[mi], bh);
                }
            }
        }
    }
    float* outp = g_S + (size_t)b * Nn * Nn;
#pragma unroll
    for (int mi = 0; mi < 2; mi++) {
#pragma unroll
        for (int nf = 0; nf < 8; nf++) {
            float* c = acc[mi][nf];
            int ml = wm * 32 + mi * 16 + gid;
            int nl = wn * 64 + nf * 8 + 2 * ctg;
            float2 v0 = { 2.f * c[0] - sXM[ml] - sXN[nl],
                          2.f * c[1] - sXM[ml] - sXN[nl + 1] };
            float2 v1 = { 2.f * c[2] - sXM[ml + 8] - sXN[nl],
                          2.f * c[3] - sXM[ml + 8] - sXN[nl + 1] };
            *(float2*)&outp[(size_t)(m0 + ml) * Nn + n0 + nl] = v0;
            *(float2*)&outp[(size_t)(m0 + ml + 8) * Nn + n0 + nl] = v1;
        }
    }
}

// -------------- top-16 per row via 4-pass radix select (float4 loads) ------
__global__ __launch_bounds__(256) void k_topk() {
    int row = blockIdx.x;
    int t = threadIdx.x;
    const float4* r4 = (const float4*)(g_S + (size_t)row * Nn);
    unsigned key[16];
#pragma unroll
    for (int i = 0; i < 4; i++) {
        float4 v = r4[t + i * 256];
        float vv[4] = {v.x, v.y, v.z, v.w};
#pragma unroll
        for (int j = 0; j < 4; j++) {
            unsigned u = __float_as_uint(vv[j]);
            key[i * 4 + j] = (u & 0x80000000u) ? ~u : (u | 0x80000000u);
        }
    }
    __shared__ int hist[256];
    __shared__ int sufs[257];
    __shared__ unsigned sPrefix;
    __shared__ int sRemain;
    __shared__ int sOutc, sEqc;
    __shared__ int eqbuf[64];
    if (t == 0) { sRemain = Kk; sOutc = 0; sEqc = 0; }
    unsigned prefix = 0;
#pragma unroll
    for (int pass = 0; pass < 4; pass++) {
        int shift = 24 - 8 * pass;
        hist[t] = 0;
        __syncthreads();
#pragma unroll
        for (int i = 0; i < 16; i++) {
            bool act = (pass == 0) || ((key[i] >> (shift + 8)) == prefix);
            if (act) atomicAdd(&hist[(key[i] >> shift) & 255], 1);
        }
        __syncthreads();
        sufs[t] = hist[t];
        if (t == 0) sufs[256] = 0;
        __syncthreads();
#pragma unroll
        for (int off = 1; off < 256; off <<= 1) {
            int add = (t + off < 256) ? sufs[t + off] : 0;
            __syncthreads();
            sufs[t] += add;
            __syncthreads();
        }
        int remain = sRemain;
        if (sufs[t] >= remain && sufs[t + 1] < remain) {
            sPrefix = (prefix << 8) | (unsigned)t;
            sRemain = remain - sufs[t + 1];
        }
        __syncthreads();
        prefix = sPrefix;
    }
    unsigned T = prefix;
    int remain = sRemain;
    int* outp = g_idxb + (size_t)row * Kk;
#pragma unroll
    for (int i = 0; i < 16; i++) {
        int idx = (t + (i >> 2) * 256) * 4 + (i & 3);
        if (key[i] > T) {
            int p = atomicAdd(&sOutc, 1);
            outp[p] = idx;
        } else if (key[i] == T) {
            int e = atomicAdd(&sEqc, 1);
            if (e < 64) eqbuf[e] = idx;
        }
    }
    __syncthreads();
    if (t == 0) {
        int base = sOutc;
        int ec = sEqc < 64 ? sEqc : 64;
        for (int rnd = 0; rnd < remain; rnd++) {
            int bi = 1 << 30, bp = -1;
            for (int e = 0; e < ec; e++)
                if (eqbuf[e] < bi) { bi = eqbuf[e]; bp = e; }
            outp[base + rnd] = bi;
            eqbuf[bp] = 1 << 30;
        }
    }
}

// -------- A = W[:, :64] . x, Bv = W[:, 64:128] . x  ------------------------
__global__ __launch_bounds__(256) void k_projAB(const float* __restrict__ wl) {
    __shared__ float sF[64][64];
    int bn0 = blockIdx.x * 64;
    int t = threadIdx.x;
    for (int e = t; e < 4096; e += 256) {
        int n = e >> 6, d = e & 63;
        sF[n][d] = g_ft[(size_t)(bn0 + n) * Dd + d];
    }
    __syncthreads();
    int half = t >> 7, o = t & 127;
    float wr[64];
#pragma unroll
    for (int d = 0; d < 64; d++) wr[d] = wl[o * 129 + half * 64 + d];
    float* dst = half ? g_Bloc : g_Aloc;
    for (int nn = 0; nn < 64; nn++) {
        float acc = 0.f;
#pragma unroll
        for (int d = 0; d < 64; d++) acc = fmaf(wr[d], sF[nn][d], acc);
        dst[(size_t)(bn0 + nn) * Oo + o] = acc;
    }
}

// --- gather neighbors, dist, y = A + Bv[j] + w_last*dist; max/min + stats --
__global__ __launch_bounds__(128) void k_intra(const float* __restrict__ wl) {
    __shared__ float sCen[64];
    __shared__ float sPart[16][8];
    __shared__ float sDist[16];
    __shared__ int sJ[16];
    int t = threadIdx.x;
    float wlast = wl[t * 129 + 128];
    float accS = 0.f, accQ = 0.f;
    for (int g = 0; g < 32; g++) {
        int bn = blockIdx.x * 32 + g;
        int b = bn >> 12;
        if (t < 64) sCen[t] = g_ft[(size_t)bn * Dd + t];
        __syncthreads();
        {
            int k = t >> 3, dg = t & 7;
            int j = g_idxb[(size_t)bn * Kk + k];
            const float* nr = g_ft + ((size_t)b * Nn + j) * Dd + dg * 8;
            float p = 0.f;
#pragma unroll
            for (int d = 0; d < 8; d++) {
                float df = nr[d] - sCen[dg * 8 + d];
                p = fmaf(df, df, p);
            }
            sPart[k][dg] = p;
            if (dg == 0) sJ[k] = j;
        }
        __syncthreads();
        if (t < 16) {
            float s = 0.f;
#pragma unroll
            for (int d = 0; d < 8; d++) s += sPart[t][d];
            sDist[t] = sqrtf(s);
        }
        __syncthreads();
        float a = g_Aloc[(size_t)bn * Oo + t];
        float mx = NEGINF, mn = -NEGINF;
#pragma unroll
        for (int kk = 0; kk < Kk; kk++) {
            int jj = sJ[kk];
            float y = a + g_Bloc[((size_t)b * Nn + jj) * Oo + t] + wlast * sDist[kk];
            mx = fmaxf(mx, y);
            mn = fminf(mn, y);
            accS += y;
            accQ = fmaf(y, y, accQ);
        }
        g_ymax[(size_t)bn * Oo + t] = mx;
        g_ymin[(size_t)bn * Oo + t] = mn;
        __syncthreads();
    }
    g_p1s[(size_t)blockIdx.x * Oo + t] = accS;
    g_p1q[(size_t)blockIdx.x * Oo + t] = accQ;
}

// ------------------------- q,k,v projections -------------------------------
__global__ __launch_bounds__(192) void k_qkv(const float* __restrict__ f,
    const float* __restrict__ wq, const float* __restrict__ bq,
    const float* __restrict__ wk, const float* __restrict__ bk,
    const float* __restrict__ wv, const float* __restrict__ bv) {
    __shared__ float sF[64][64];
    int b = blockIdx.y, n0 = blockIdx.x * 64, t = threadIdx.x;
    const float* fb = f + (size_t)b * Dd * Nn;
    for (int e = t; e < 4096; e += 192) {
        int d = e >> 6, nn = e & 63;
        sF[d][nn] = fb[(size_t)d * Nn + n0 + nn];
    }
    __syncthreads();
    int grp = t / 64, o = t % 64;
    const float* W = grp == 0 ? wq : (grp == 1 ? wk : wv);
    const float* bias = grp == 0 ? bq : (grp == 1 ? bk : bv);
    float* outp = (grp == 0 ? g_q : (grp == 1 ? g_k : g_v)) + ((size_t)b * Dd + o) * Nn + n0;
    float wr[64];
#pragma unroll
    for (int d = 0; d < 64; d++) wr[d] = W[o * 64 + d];
    for (int nn = 0; nn < 64; nn++) {
        float acc = bias[o];
#pragma unroll
        for (int d = 0; d < 64; d++) acc = fmaf(wr[d], sF[d][nn], acc);
        outp[nn] = acc;
    }
}

// ----- flash attention: fgt = softmax(qk/8) @ v, no S materialization ------
// CTA = 128 query rows; 8 warps x 16 rows. Iterate 64 key-tiles of 64.
// smem: sK [64][72], sP [128][72] (warp-private rows), sV [64][72].
__global__ __launch_bounds__(256) void k_flash() {
    extern __shared__ uint32_t fsm[];
    uint32_t* sK = fsm;                    // 64*72
    uint32_t* sP = fsm + 64 * 72;          // 128*72
    uint32_t* sV = fsm + 64 * 72 + 128 * 72;
    float* sQ = (float*)fsm;               // prologue only: [64][136]
    int t = threadIdx.x, lane = t & 31, wid = t >> 5;
    int gid = lane >> 2, ctg = lane & 3;
    int b = blockIdx.y, m0 = blockIdx.x * 128;
    int mwb = wid * 16;
    const float* qb = g_q + (size_t)b * Dd * Nn;
    const float* kb_ = g_k + (size_t)b * Dd * Nn;
    const float* vb = g_v + (size_t)b * Dd * Nn;

    // prologue: stage Q tile, extract scaled A-fragments
#pragma unroll
    for (int i = 0; i < 32; i++) {
        int e = t + i * 256;
        int d = e >> 7, m = e & 127;
        sQ[d * 136 + m] = qb[(size_t)d * Nn + m0 + m] * 0.125f;
    }
    __syncthreads();
    uint32_t qf[8][4];
#pragma unroll
    for (int ks = 0; ks < 8; ks++) {
        int kb = ks * 8 + ctg;
        int mb = mwb + gid;
        qf[ks][0] = tf32one(sQ[kb * 136 + mb]);
        qf[ks][1] = tf32one(sQ[kb * 136 + mb + 8]);
        qf[ks][2] = tf32one(sQ[(kb + 4) * 136 + mb]);
        qf[ks][3] = tf32one(sQ[(kb + 4) * 136 + mb + 8]);
    }

    float mo0 = NEGINF, mo1 = NEGINF, l0 = 0.f, l1 = 0.f;
    float oacc[8][4] = {};
    for (int nc = 0; nc < 64; nc++) {
        int n0 = nc * 64;
        __syncthreads();
#pragma unroll
        for (int i = 0; i < 16; i++) {
            int e = t + i * 256;
            int d = e >> 6, nn = e & 63;
            sK[d * 72 + nn] = tf32one(kb_[(size_t)d * Nn + n0 + nn]);
            sV[d * 72 + nn] = tf32one(vb[(size_t)d * Nn + n0 + nn]);
        }
        __syncthreads();
        // S = (Q/8) . K
        float c[8][4] = {};
#pragma unroll
        for (int ks = 0; ks < 8; ks++) {
            int kb = ks * 8 + ctg;
#pragma unroll
            for (int nf = 0; nf < 8; nf++) {
                int nb = nf * 8 + gid;
                uint32_t bb[2];
                bb[0] = sK[kb * 72 + nb];
                bb[1] = sK[(kb + 4) * 72 + nb];
                mma_m16n8k8(c[nf], qf[ks], bb);
            }
        }
        // online softmax
        float tm0 = NEGINF, tm1 = NEGINF;
#pragma unroll
        for (int nf = 0; nf < 8; nf++) {
            tm0 = fmaxf(tm0, fmaxf(c[nf][0], c[nf][1]));
            tm1 = fmaxf(tm1, fmaxf(c[nf][2], c[nf][3]));
        }
#pragma unroll
        for (int off = 1; off <= 2; off <<= 1) {
            tm0 = fmaxf(tm0, __shfl_xor_sync(0xffffffffu, tm0, off));
            tm1 = fmaxf(tm1, __shfl_xor_sync(0xffffffffu, tm1, off));
        }
        float mn0 = fmaxf(mo0, tm0), mn1 = fmaxf(mo1, tm1);
        float s0 = __expf(mo0 - mn0), s1 = __expf(mo1 - mn1);
        float sum0 = 0.f, sum1 = 0.f;
#pragma unroll
        for (int nf = 0; nf < 8; nf++) {
            float p00 = __expf(c[nf][0] - mn0);
            float p01 = __expf(c[nf][1] - mn0);
            float p10 = __expf(c[nf][2] - mn1);
            float p11 = __expf(c[nf][3] - mn1);
            sum0 += p00 + p01;
            sum1 += p10 + p11;
            int nl = nf * 8 + 2 * ctg;
            sP[(mwb + gid) * 72 + nl]     = tf32one(p00);
            sP[(mwb + gid) * 72 + nl + 1] = tf32one(p01);
            sP[(mwb + gid + 8) * 72 + nl]     = tf32one(p10);
            sP[(mwb + gid + 8) * 72 + nl + 1] = tf32one(p11);
        }
#pragma unroll
        for (int off = 1; off <= 2; off <<= 1) {
            sum0 += __shfl_xor_sync(0xffffffffu, sum0, off);
            sum1 += __shfl_xor_sync(0xffffffffu, sum1, off);
        }
        l0 = l0 * s0 + sum0;
        l1 = l1 * s1 + sum1;
#pragma unroll
        for (int nf = 0; nf < 8; nf++) {
            oacc[nf][0] *= s0; oacc[nf][1] *= s0;
            oacc[nf][2] *= s1; oacc[nf][3] *= s1;
        }
        __syncwarp();
        // O += P . V
#pragma unroll
        for (int ks = 0; ks < 8; ks++) {
            int kb = ks * 8 + ctg;
            uint32_t a[4];
            a[0] = sP[(mwb + gid) * 72 + kb];
            a[1] = sP[(mwb + gid + 8) * 72 + kb];
            a[2] = sP[(mwb + gid) * 72 + kb + 4];
            a[3] = sP[(mwb + gid + 8) * 72 + kb + 4];
#pragma unroll
            for (int nf = 0; nf < 8; nf++) {
                int nb = nf * 8 + gid;
                uint32_t bb[2];
                bb[0] = sV[nb * 72 + kb];
                bb[1] = sV[nb * 72 + kb + 4];
                mma_m16n8k8(oacc[nf], a, bb);
            }
        }
        mo0 = mn0; mo1 = mn1;
    }
    float is0 = 1.0f / l0, is1 = 1.0f / l1;
    int m_ = m0 + mwb + gid;
#pragma unroll
    for (int nf = 0; nf < 8; nf++) {
        int d0 = nf * 8 + 2 * ctg;
        g_fgt[((size_t)b * Dd + d0) * Nn + m_]         = oacc[nf][0] * is0;
        g_fgt[((size_t)b * Dd + d0 + 1) * Nn + m_]     = oacc[nf][1] * is0;
        g_fgt[((size_t)b * Dd + d0) * Nn + m_ + 8]     = oacc[nf][2] * is1;
        g_fgt[((size_t)b * Dd + d0 + 1) * Nn + m_ + 8] = oacc[nf][3] * is1;
    }
}

// ------------------- inter pre-bn: z2 = w_sem . fgt ------------------------
__global__ __launch_bounds__(128) void k_inter(const float* __restrict__ wsem) {
    __shared__ float sF[64][64];
    int b = blockIdx.y, n0 = blockIdx.x * 64, t = threadIdx.x;
    const float* fb = g_fgt + (size_t)b * Dd * Nn;
    for (int e = t; e < 4096; e += 128) {
        int d = e >> 6, nn = e & 63;
        sF[d][nn] = fb[(size_t)d * Nn + n0 + nn];
    }
    __syncthreads();
    float wr[64];
#pragma unroll
    for (int d = 0; d < 64; d++) wr[d] = wsem[t * 64 + d];
    float aS = 0.f, aQ = 0.f;
    for (int nn = 0; nn < 64; nn++) {
        float acc = 0.f;
#pragma unroll
        for (int d = 0; d < 64; d++) acc = fmaf(wr[d], sF[d][nn], acc);
        g_z2[((size_t)b * Nn + n0 + nn) * Oo + t] = acc;
        aS += acc;
        aQ = fmaf(acc, acc, aQ);
    }
    int blk = blockIdx.y * gridDim.x + blockIdx.x;
    g_p2s[(size_t)blk * Oo + t] = aS;
    g_p2q[(size_t)blk * Oo + t] = aQ;
}

// --------- bn stat finalize ------------------------------------------------
__global__ void k_bnstats(int which, int nblk, float invcnt,
                          const float* __restrict__ gamma, const float* __restrict__ beta) {
    int o = threadIdx.x;
    const float *ps, *pq;
    float *sc, *sh;
    if (which == 1) { ps = g_p1s; pq = g_p1q; sc = g_sc1; sh = g_sh1; }
    else if (which == 2) { ps = g_p2s; pq = g_p2q; sc = g_sc2; sh = g_sh2; }
    else { ps = g_p3s; pq = g_p3q; sc = g_sc3; sh = g_sh3; }
    float s = 0.f, q = 0.f;
    for (int i = 0; i < nblk; i++) {
        s += ps[(size_t)i * Oo + o];
        q += pq[(size_t)i * Oo + o];
    }
    float mean = s * invcnt;
    float var = q * invcnt - mean * mean;
    float scl = gamma[o] / sqrtf(var + 1e-5f);
    sc[o] = scl;
    sh[o] = beta[o] - mean * scl;
}

// --------- z3 = w_full . [lrelu(bn1(intra)); lrelu(bn2(inter))] ------------
__global__ __launch_bounds__(128) void k_z3(const float* __restrict__ wfull) {
    __shared__ float sC[16][256];
    __shared__ float sW[32][129];
    int bn0 = blockIdx.x * 16, t = threadIdx.x;
    for (int e = t; e < 16 * 256; e += 128) {
        int n = e >> 8, c = e & 255;
        int bn = bn0 + n;
        float pre;
        if (c < 128) {
            float s1 = g_sc1[c];
            float ym = (s1 >= 0.f) ? g_ymax[(size_t)bn * Oo + c] : g_ymin[(size_t)bn * Oo + c];
            pre = fmaf(s1, ym, g_sh1[c]);
        } else {
            int o = c - 128;
            pre = fmaf(g_sc2[o], g_z2[(size_t)bn * Oo + o], g_sh2[o]);
        }
        sC[n][c] = pre >= 0.f ? pre : NEG * pre;
    }
    float acc[16] = {};
    for (int ch = 0; ch < 8; ch++) {
        __syncthreads();
        for (int e = t; e < 32 * 128; e += 128) {
            int o = e >> 5, c = e & 31;
            sW[c][o] = wfull[(size_t)o * 256 + ch * 32 + c];
        }
        __syncthreads();
#pragma unroll 4
        for (int c = 0; c < 32; c++) {
            float w = sW[c][t];
            int cg = ch * 32 + c;
#pragma unroll
            for (int n = 0; n < 16; n++) acc[n] = fmaf(w, sC[n][cg], acc[n]);
        }
    }
    float aS = 0.f, aQ = 0.f;
#pragma unroll
    for (int n = 0; n < 16; n++) {
        float z = acc[n];
        g_z3[(size_t)(bn0 + n) * Oo + t] = z;
        aS += z;
        aQ = fmaf(z, z, aQ);
    }
    g_p3s[(size_t)blockIdx.x * Oo + t] = aS;
    g_p3q[(size_t)blockIdx.x * Oo + t] = aQ;
}

// --------- out[b,o,n] = lrelu(bn3(z3)) with transpose ----------------------
__global__ __launch_bounds__(256) void k_out(float* __restrict__ out) {
    __shared__ float tile[32][33];
    int b = blockIdx.z, o0 = blockIdx.y * 32, n0 = blockIdx.x * 32;
    int tx = threadIdx.x & 31, ty = threadIdx.x >> 5;
    float scl = g_sc3[o0 + tx], sh = g_sh3[o0 + tx];
#pragma unroll
    for (int i = 0; i < 4; i++) {
        int n = n0 + ty + i * 8;
        float v = fmaf(scl, g_z3[((size_t)b * Nn + n) * Oo + o0 + tx], sh);
        tile[ty + i * 8][tx] = v >= 0.f ? v : NEG * v;
    }
    __syncthreads();
#pragma unroll
    for (int i = 0; i < 4; i++) {
        int o = o0 + ty + i * 8;
        out[((size_t)b * Oo + o) * Nn + n0 + tx] = tile[tx][ty + i * 8];
    }
}

// ---------------------------------------------------------------------------
extern "C" void kernel_launch(void* const* d_in, const int* in_sizes, int n_in,
                              void* d_out, int out_size) {
    const float* f       = (const float*)d_in[0];
    const float* w_local = (const float*)d_in[1];
    const float* g_local = (const float*)d_in[2];
    const float* b_local = (const float*)d_in[3];
    const float* w_sem   = (const float*)d_in[4];
    const float* g_sem   = (const float*)d_in[5];
    const float* b_sem   = (const float*)d_in[6];
    const float* w_full  = (const float*)d_in[7];
    const float* g_full  = (const float*)d_in[8];
    const float* b_full  = (const float*)d_in[9];
    const float* wq = (const float*)d_in[10];
    const float* bq = (const float*)d_in[11];
    const float* wk = (const float*)d_in[12];
    const float* bk = (const float*)d_in[13];
    const float* wv = (const float*)d_in[14];
    const float* bv = (const float*)d_in[15];
    float* out = (float*)d_out;

    const int MM_SMEM = 128 * KST * 4;                 // 69632 bytes
    const int FL_SMEM = (64 + 128 + 64) * 72 * 4;      // 73728 bytes
    cudaFuncSetAttribute(k_mm, cudaFuncAttributeMaxDynamicSharedMemorySize, MM_SMEM);
    cudaFuncSetAttribute(k_flash, cudaFuncAttributeMaxDynamicSharedMemorySize, FL_SMEM);

    k_xx<<<64, 256>>>(f);
    k_tr<<<dim3(Nn / 32, Dd / 32, Bx), 256>>>(f);
    k_mm<<<dim3(32, 32, Bx), 256, MM_SMEM>>>(f);
    k_topk<<<Bx * Nn, 256>>>();
    k_projAB<<<Bx * Nn / 64, 256>>>(w_local);
    k_intra<<<Bx * Nn / 32, 128>>>(w_local);
    k_bnstats<<<1, 128>>>(1, 512, 1.0f / (Bx * Nn * Kk), g_local, b_local);
    k_qkv<<<dim3(64, Bx), 192>>>(f, wq, bq, wk, bk, wv, bv);
    k_flash<<<dim3(32, Bx), 256, FL_SMEM>>>();
    k_inter<<<dim3(64, Bx), 128>>>(w_sem);
    k_bnstats<<<1, 128>>>(2, 256, 1.0f / (Bx * Nn), g_sem, b_sem);
    k_z3<<<Bx * Nn / 16, 128>>>(w_full);
    k_bnstats<<<1, 128>>>(3, 1024, 1.0f / (Bx * Nn), g_full, b_full);
    k_out<<<dim3(Nn / 32, Oo / 32, Bx), 256>>>(out);
}

// round 10
// speedup vs baseline: 1.5543x; 1.0682x over previous
#include <cuda_runtime.h>
#include <math.h>
#include <stdint.h>

#define Bx 4
#define Dd 64
#define Nn 4096
#define Oo 128
#define Kk 16
#define NEG 0.01f
#define NEGINF (-1.0e30f)

// ------------------------- static device scratch ---------------------------
__device__ float g_S[(size_t)Bx * Nn * Nn];
__device__ float g_xx[Bx * Nn];
__device__ float g_ft[Bx * Nn * Dd];
__device__ float g_q[Bx * Dd * Nn];
__device__ float g_k[Bx * Dd * Nn];
__device__ float g_v[Bx * Dd * Nn];
__device__ float g_Aloc[(size_t)Bx * Nn * Oo];
__device__ float g_Bloc[(size_t)Bx * Nn * Oo];
__device__ int   g_idxb[Bx * Nn * Kk];
__device__ float g_ymax[(size_t)Bx * Nn * Oo];
__device__ float g_ymin[(size_t)Bx * Nn * Oo];
__device__ float g_z2[(size_t)Bx * Nn * Oo];
__device__ float g_z3[(size_t)Bx * Nn * Oo];
__device__ float g_fgt[Bx * Dd * Nn];
__device__ float g_p1s[512 * Oo], g_p1q[512 * Oo];
__device__ float g_p2s[256 * Oo], g_p2q[256 * Oo];
__device__ float g_p3s[1024 * Oo], g_p3q[1024 * Oo];
__device__ float g_sc1[Oo], g_sh1[Oo], g_sc2[Oo], g_sh2[Oo], g_sc3[Oo], g_sh3[Oo];

// ------------------------- helpers -----------------------------------------
__device__ __forceinline__ void tf32split_u(float x, uint32_t& hi, uint32_t& lo) {
    asm("cvt.rna.tf32.f32 %0, %1;" : "=r"(hi) : "f"(x));
    float l = x - __uint_as_float(hi);
    asm("cvt.rna.tf32.f32 %0, %1;" : "=r"(lo) : "f"(l));
}
__device__ __forceinline__ uint32_t tf32one(float x) {
    uint32_t h;
    asm("cvt.rna.tf32.f32 %0, %1;" : "=r"(h) : "f"(x));
    return h;
}
__device__ __forceinline__ void mma_m16n8k8(float* c, const uint32_t* a, const uint32_t* b) {
    asm volatile(
        "mma.sync.aligned.m16n8k8.row.col.f32.tf32.tf32.f32 "
        "{%0,%1,%2,%3}, {%4,%5,%6,%7}, {%8,%9}, {%0,%1,%2,%3};"
        : "+f"(c[0]), "+f"(c[1]), "+f"(c[2]), "+f"(c[3])
        : "r"(a[0]), "r"(a[1]), "r"(a[2]), "r"(a[3]), "r"(b[0]), "r"(b[1]));
}

// ------------------------- xx[b,n] = sum_d f^2 -----------------------------
__global__ void k_xx(const float* __restrict__ f) {
    int id = blockIdx.x * 256 + threadIdx.x;
    int b = id >> 12;
    int n = id & (Nn - 1);
    const float* fb = f + (size_t)b * Dd * Nn + n;
    float s = 0.f;
#pragma unroll
    for (int d = 0; d < Dd; d++) {
        float v = fb[(size_t)d * Nn];
        s = fmaf(v, v, s);
    }
    g_xx[id] = s;
}

// ------------------------- transpose f -> (B,N,D) --------------------------
__global__ __launch_bounds__(256) void k_tr(const float* __restrict__ f) {
    __shared__ float tile[32][33];
    int b = blockIdx.z, d0 = blockIdx.y * 32, n0 = blockIdx.x * 32;
    int tx = threadIdx.x & 31, ty = threadIdx.x >> 5;
#pragma unroll
    for (int i = 0; i < 4; i++)
        tile[ty + i * 8][tx] = f[((size_t)b * Dd + d0 + ty + i * 8) * Nn + n0 + tx];
    __syncthreads();
#pragma unroll
    for (int i = 0; i < 4; i++)
        g_ft[((size_t)b * Nn + n0 + ty + i * 8) * Dd + d0 + tx] = tile[tx][ty + i * 8];
}

// -------- warp-MMA tf32 GEMM: pd (3-term split) -> g_S ---------------------
#define KST 136
__global__ __launch_bounds__(256, 2) void k_mm(const float* __restrict__ f) {
    extern __shared__ uint32_t dsm[];
    __shared__ float sXM[128], sXN[128];
    uint32_t* sAh = dsm;
    uint32_t* sAl = dsm + 32 * KST;
    uint32_t* sBh = dsm + 64 * KST;
    uint32_t* sBl = dsm + 96 * KST;
    int t = threadIdx.x, lane = t & 31, wid = t >> 5;
    int wm = wid & 3, wn = wid >> 2;
    int gid = lane >> 2, ctg = lane & 3;
    int b = blockIdx.z, m0 = blockIdx.y * 128, n0 = blockIdx.x * 128;
    const float* Ap = f + (size_t)b * Dd * Nn;
    if (t < 128) sXM[t] = g_xx[b * Nn + m0 + t];
    else sXN[t - 128] = g_xx[b * Nn + n0 + t - 128];
    float acc[2][8][4] = {};
#pragma unroll
    for (int kc = 0; kc < 2; kc++) {
        int kc0 = kc * 32;
        __syncthreads();
#pragma unroll
        for (int i = 0; i < 16; i++) {
            int e = t + i * 256;
            int d = e >> 7, m = e & 127;
            float a  = Ap[(size_t)(kc0 + d) * Nn + m0 + m];
            float bb = Ap[(size_t)(kc0 + d) * Nn + n0 + m];
            uint32_t hi, lo;
            tf32split_u(a, hi, lo);  sAh[d * KST + m] = hi; sAl[d * KST + m] = lo;
            tf32split_u(bb, hi, lo); sBh[d * KST + m] = hi; sBl[d * KST + m] = lo;
        }
        __syncthreads();
#pragma unroll
        for (int ks = 0; ks < 4; ks++) {
            int kb = ks * 8 + ctg;
            uint32_t ah[2][4], al[2][4];
#pragma unroll
            for (int mi = 0; mi < 2; mi++) {
                int mb = wm * 32 + mi * 16 + gid;
                ah[mi][0] = sAh[kb * KST + mb];
                ah[mi][1] = sAh[kb * KST + mb + 8];
                ah[mi][2] = sAh[(kb + 4) * KST + mb];
                ah[mi][3] = sAh[(kb + 4) * KST + mb + 8];
                al[mi][0] = sAl[kb * KST + mb];
                al[mi][1] = sAl[kb * KST + mb + 8];
                al[mi][2] = sAl[(kb + 4) * KST + mb];
                al[mi][3] = sAl[(kb + 4) * KST + mb + 8];
            }
#pragma unroll
            for (int nf = 0; nf < 8; nf++) {
                int nb = wn * 64 + nf * 8 + gid;
                uint32_t bh[2], bl[2];
                bh[0] = sBh[kb * KST + nb];
                bh[1] = sBh[(kb + 4) * KST + nb];
                bl[0] = sBl[kb * KST + nb];
                bl[1] = sBl[(kb + 4) * KST + nb];
#pragma unroll
                for (int mi = 0; mi < 2; mi++) {
                    mma_m16n8k8(acc[mi][nf], ah[mi], bh);
                    mma_m16n8k8(acc[mi][nf], ah[mi], bl);
                    mma_m16n8k8(acc[mi][nf], al[mi], bh);
                }
            }
        }
    }
    float* outp = g_S + (size_t)b * Nn * Nn;
#pragma unroll
    for (int mi = 0; mi < 2; mi++) {
#pragma unroll
        for (int nf = 0; nf < 8; nf++) {
            float* c = acc[mi][nf];
            int ml = wm * 32 + mi * 16 + gid;
            int nl = wn * 64 + nf * 8 + 2 * ctg;
            float2 v0 = { 2.f * c[0] - sXM[ml] - sXN[nl],
                          2.f * c[1] - sXM[ml] - sXN[nl + 1] };
            float2 v1 = { 2.f * c[2] - sXM[ml + 8] - sXN[nl],
                          2.f * c[3] - sXM[ml + 8] - sXN[nl + 1] };
            *(float2*)&outp[(size_t)(m0 + ml) * Nn + n0 + nl] = v0;
            *(float2*)&outp[(size_t)(m0 + ml + 8) * Nn + n0 + nl] = v1;
        }
    }
}

// -------------- top-16 per row via 4-pass radix select (warp-shuffle scan) -
__global__ __launch_bounds__(256) void k_topk() {
    int row = blockIdx.x;
    int t = threadIdx.x, lane = t & 31, wid = t >> 5;
    const float4* r4 = (const float4*)(g_S + (size_t)row * Nn);
    unsigned key[16];
#pragma unroll
    for (int i = 0; i < 4; i++) {
        float4 v = r4[t + i * 256];
        float vv[4] = {v.x, v.y, v.z, v.w};
#pragma unroll
        for (int j = 0; j < 4; j++) {
            unsigned u = __float_as_uint(vv[j]);
            key[i * 4 + j] = (u & 0x80000000u) ? ~u : (u | 0x80000000u);
        }
    }
    __shared__ int hist[256];
    __shared__ int wsum[8];
    __shared__ unsigned sPrefix;
    __shared__ int sRemain;
    __shared__ int sOutc, sEqc;
    __shared__ int eqbuf[64];
    if (t == 0) { sRemain = Kk; sOutc = 0; sEqc = 0; }
    unsigned prefix = 0;
#pragma unroll
    for (int pass = 0; pass < 4; pass++) {
        int shift = 24 - 8 * pass;
        hist[t] = 0;
        __syncthreads();
#pragma unroll
        for (int i = 0; i < 16; i++) {
            bool act = (pass == 0) || ((key[i] >> (shift + 8)) == prefix);
            if (act) atomicAdd(&hist[(key[i] >> shift) & 255], 1);
        }
        __syncthreads();
        int h = hist[t];
        int remain = sRemain;
        // intra-warp suffix scan of 32 bins
        int v = h;
#pragma unroll
        for (int off = 1; off < 32; off <<= 1) {
            int u = __shfl_down_sync(0xffffffffu, v, off);
            if (lane + off < 32) v += u;
        }
        if (lane == 0) wsum[wid] = v;
        __syncthreads();
        int tail = 0;
#pragma unroll
        for (int w2 = 0; w2 < 8; w2++)
            if (w2 > wid) tail += wsum[w2];
        int suf = v + tail;                  // = count of active keys with bin >= t
        if (suf >= remain && suf - h < remain) {
            sPrefix = (prefix << 8) | (unsigned)t;
            sRemain = remain - (suf - h);
        }
        __syncthreads();
        prefix = sPrefix;
    }
    unsigned T = prefix;
    int remain = sRemain;
    int* outp = g_idxb + (size_t)row * Kk;
#pragma unroll
    for (int i = 0; i < 16; i++) {
        int idx = (t + (i >> 2) * 256) * 4 + (i & 3);
        if (key[i] > T) {
            int p = atomicAdd(&sOutc, 1);
            outp[p] = idx;
        } else if (key[i] == T) {
            int e = atomicAdd(&sEqc, 1);
            if (e < 64) eqbuf[e] = idx;
        }
    }
    __syncthreads();
    if (t == 0) {
        int base = sOutc;
        int ec = sEqc < 64 ? sEqc : 64;
        for (int rnd = 0; rnd < remain; rnd++) {
            int bi = 1 << 30, bp = -1;
            for (int e = 0; e < ec; e++)
                if (eqbuf[e] < bi) { bi = eqbuf[e]; bp = e; }
            outp[base + rnd] = bi;
            eqbuf[bp] = 1 << 30;
        }
    }
}

// -------- A = W[:, :64] . x, Bv = W[:, 64:128] . x  ------------------------
__global__ __launch_bounds__(256) void k_projAB(const float* __restrict__ wl) {
    __shared__ float sF[64][64];
    int bn0 = blockIdx.x * 64;
    int t = threadIdx.x;
    for (int e = t; e < 4096; e += 256) {
        int n = e >> 6, d = e & 63;
        sF[n][d] = g_ft[(size_t)(bn0 + n) * Dd + d];
    }
    __syncthreads();
    int half = t >> 7, o = t & 127;
    float wr[64];
#pragma unroll
    for (int d = 0; d < 64; d++) wr[d] = wl[o * 129 + half * 64 + d];
    float* dst = half ? g_Bloc : g_Aloc;
    for (int nn = 0; nn < 64; nn++) {
        float acc = 0.f;
#pragma unroll
        for (int d = 0; d < 64; d++) acc = fmaf(wr[d], sF[nn][d], acc);
        dst[(size_t)(bn0 + nn) * Oo + o] = acc;
    }
}

// --- gather neighbors, dist, y = A + Bv[j] + w_last*dist; max/min + stats --
__global__ __launch_bounds__(128) void k_intra(const float* __restrict__ wl) {
    __shared__ float sCen[64];
    __shared__ float sPart[16][8];
    __shared__ float sDist[16];
    __shared__ int sJ[16];
    int t = threadIdx.x;
    float wlast = wl[t * 129 + 128];
    float accS = 0.f, accQ = 0.f;
    for (int g = 0; g < 32; g++) {
        int bn = blockIdx.x * 32 + g;
        int b = bn >> 12;
        if (t < 64) sCen[t] = g_ft[(size_t)bn * Dd + t];
        __syncthreads();
        {
            int k = t >> 3, dg = t & 7;
            int j = g_idxb[(size_t)bn * Kk + k];
            const float* nr = g_ft + ((size_t)b * Nn + j) * Dd + dg * 8;
            float p = 0.f;
#pragma unroll
            for (int d = 0; d < 8; d++) {
                float df = nr[d] - sCen[dg * 8 + d];
                p = fmaf(df, df, p);
            }
            sPart[k][dg] = p;
            if (dg == 0) sJ[k] = j;
        }
        __syncthreads();
        if (t < 16) {
            float s = 0.f;
#pragma unroll
            for (int d = 0; d < 8; d++) s += sPart[t][d];
            sDist[t] = sqrtf(s);
        }
        __syncthreads();
        float a = g_Aloc[(size_t)bn * Oo + t];
        float mx = NEGINF, mn = -NEGINF;
#pragma unroll
        for (int kk = 0; kk < Kk; kk++) {
            int jj = sJ[kk];
            float y = a + g_Bloc[((size_t)b * Nn + jj) * Oo + t] + wlast * sDist[kk];
            mx = fmaxf(mx, y);
            mn = fminf(mn, y);
            accS += y;
            accQ = fmaf(y, y, accQ);
        }
        g_ymax[(size_t)bn * Oo + t] = mx;
        g_ymin[(size_t)bn * Oo + t] = mn;
        __syncthreads();
    }
    g_p1s[(size_t)blockIdx.x * Oo + t] = accS;
    g_p1q[(size_t)blockIdx.x * Oo + t] = accQ;
}

// ---------------- q,k,v projections (coalesced writes) ---------------------
// grid (Nn/64, Bx), block 256 = 8 warps. Warp w handles o-rows w+8j (j<24).
// Lanes cover n = lane, lane+32 within the 64-wide n block.
__global__ __launch_bounds__(256) void k_qkv(const float* __restrict__ f,
    const float* __restrict__ wq, const float* __restrict__ bq,
    const float* __restrict__ wk, const float* __restrict__ bk,
    const float* __restrict__ wv, const float* __restrict__ bv) {
    extern __shared__ float qsm[];
    float* sF = qsm;                 // [64][65]
    float* sW = qsm + 64 * 65;       // [192][64]
    float* sBias = sW + 192 * 64;    // [192]
    int t = threadIdx.x, lane = t & 31, wid = t >> 5;
    int b = blockIdx.y, n0 = blockIdx.x * 64;
    const float* fb = f + (size_t)b * Dd * Nn;
    for (int e = t; e < 64 * 64; e += 256) {
        int d = e >> 6, nn = e & 63;
        sF[d * 65 + nn] = fb[(size_t)d * Nn + n0 + nn];
    }
    for (int e = t; e < 192 * 64; e += 256) {
        int r = e >> 6, d = e & 63;
        const float* W = r < 64 ? wq : (r < 128 ? wk : wv);
        sW[e] = W[(r & 63) * 64 + d];
    }
    if (t < 192) sBias[t] = t < 64 ? bq[t] : (t < 128 ? bk[t - 64] : bv[t - 128]);
    __syncthreads();
#pragma unroll 4
    for (int j = 0; j < 24; j++) {
        int r = wid + 8 * j;
        const float* wr = sW + r * 64;
        float a0 = sBias[r], a1 = a0;
#pragma unroll 16
        for (int d = 0; d < 64; d++) {
            float w = wr[d];
            a0 = fmaf(w, sF[d * 65 + lane], a0);
            a1 = fmaf(w, sF[d * 65 + lane + 32], a1);
        }
        int mat = r >> 6, o = r & 63;
        float* outp = (mat == 0 ? g_q : (mat == 1 ? g_k : g_v)) + ((size_t)b * Dd + o) * Nn + n0;
        outp[lane] = a0;
        outp[lane + 32] = a1;
    }
}

// ----- flash attention: fgt = softmax(qk/8) @ v, no S materialization ------
__global__ __launch_bounds__(256) void k_flash() {
    extern __shared__ uint32_t fsm[];
    uint32_t* sK = fsm;                    // 64*72
    uint32_t* sP = fsm + 64 * 72;          // 128*72
    uint32_t* sV = fsm + 64 * 72 + 128 * 72;
    float* sQ = (float*)fsm;               // prologue only: [64][136]
    float* sO = (float*)fsm;               // epilogue only: [64][129]
    int t = threadIdx.x, lane = t & 31, wid = t >> 5;
    int gid = lane >> 2, ctg = lane & 3;
    int b = blockIdx.y, m0 = blockIdx.x * 128;
    int mwb = wid * 16;
    const float* qb = g_q + (size_t)b * Dd * Nn;
    const float* kb_ = g_k + (size_t)b * Dd * Nn;
    const float* vb = g_v + (size_t)b * Dd * Nn;

#pragma unroll
    for (int i = 0; i < 32; i++) {
        int e = t + i * 256;
        int d = e >> 7, m = e & 127;
        sQ[d * 136 + m] = qb[(size_t)d * Nn + m0 + m] * 0.125f;
    }
    __syncthreads();
    uint32_t qf[8][4];
#pragma unroll
    for (int ks = 0; ks < 8; ks++) {
        int kb = ks * 8 + ctg;
        int mb = mwb + gid;
        qf[ks][0] = tf32one(sQ[kb * 136 + mb]);
        qf[ks][1] = tf32one(sQ[kb * 136 + mb + 8]);
        qf[ks][2] = tf32one(sQ[(kb + 4) * 136 + mb]);
        qf[ks][3] = tf32one(sQ[(kb + 4) * 136 + mb + 8]);
    }

    float mo0 = NEGINF, mo1 = NEGINF, l0 = 0.f, l1 = 0.f;
    float oacc[8][4] = {};
    for (int nc = 0; nc < 64; nc++) {
        int n0 = nc * 64;
        __syncthreads();
#pragma unroll
        for (int i = 0; i < 16; i++) {
            int e = t + i * 256;
            int d = e >> 6, nn = e & 63;
            sK[d * 72 + nn] = tf32one(kb_[(size_t)d * Nn + n0 + nn]);
            sV[d * 72 + nn] = tf32one(vb[(size_t)d * Nn + n0 + nn]);
        }
        __syncthreads();
        float c[8][4] = {};
#pragma unroll
        for (int ks = 0; ks < 8; ks++) {
            int kb = ks * 8 + ctg;
#pragma unroll
            for (int nf = 0; nf < 8; nf++) {
                int nb = nf * 8 + gid;
                uint32_t bb[2];
                bb[0] = sK[kb * 72 + nb];
                bb[1] = sK[(kb + 4) * 72 + nb];
                mma_m16n8k8(c[nf], qf[ks], bb);
            }
        }
        float tm0 = NEGINF, tm1 = NEGINF;
#pragma unroll
        for (int nf = 0; nf < 8; nf++) {
            tm0 = fmaxf(tm0, fmaxf(c[nf][0], c[nf][1]));
            tm1 = fmaxf(tm1, fmaxf(c[nf][2], c[nf][3]));
        }
#pragma unroll
        for (int off = 1; off <= 2; off <<= 1) {
            tm0 = fmaxf(tm0, __shfl_xor_sync(0xffffffffu, tm0, off));
            tm1 = fmaxf(tm1, __shfl_xor_sync(0xffffffffu, tm1, off));
        }
        float mn0 = fmaxf(mo0, tm0), mn1 = fmaxf(mo1, tm1);
        float s0 = __expf(mo0 - mn0), s1 = __expf(mo1 - mn1);
        float sum0 = 0.f, sum1 = 0.f;
#pragma unroll
        for (int nf = 0; nf < 8; nf++) {
            float p00 = __expf(c[nf][0] - mn0);
            float p01 = __expf(c[nf][1] - mn0);
            float p10 = __expf(c[nf][2] - mn1);
            float p11 = __expf(c[nf][3] - mn1);
            sum0 += p00 + p01;
            sum1 += p10 + p11;
            int nl = nf * 8 + 2 * ctg;
            sP[(mwb + gid) * 72 + nl]     = tf32one(p00);
            sP[(mwb + gid) * 72 + nl + 1] = tf32one(p01);
            sP[(mwb + gid + 8) * 72 + nl]     = tf32one(p10);
            sP[(mwb + gid + 8) * 72 + nl + 1] = tf32one(p11);
        }
#pragma unroll
        for (int off = 1; off <= 2; off <<= 1) {
            sum0 += __shfl_xor_sync(0xffffffffu, sum0, off);
            sum1 += __shfl_xor_sync(0xffffffffu, sum1, off);
        }
        l0 = l0 * s0 + sum0;
        l1 = l1 * s1 + sum1;
#pragma unroll
        for (int nf = 0; nf < 8; nf++) {
            oacc[nf][0] *= s0; oacc[nf][1] *= s0;
            oacc[nf][2] *= s1; oacc[nf][3] *= s1;
        }
        __syncwarp();
#pragma unroll
        for (int ks = 0; ks < 8; ks++) {
            int kb = ks * 8 + ctg;
            uint32_t a[4];
            a[0] = sP[(mwb + gid) * 72 + kb];
            a[1] = sP[(mwb + gid + 8) * 72 + kb];
            a[2] = sP[(mwb + gid) * 72 + kb + 4];
            a[3] = sP[(mwb + gid + 8) * 72 + kb + 4];
#pragma unroll
            for (int nf = 0; nf < 8; nf++) {
                int nb = nf * 8 + gid;
                uint32_t bb[2];
                bb[0] = sV[nb * 72 + kb];
                bb[1] = sV[nb * 72 + kb + 4];
                mma_m16n8k8(oacc[nf], a, bb);
            }
        }
        mo0 = mn0; mo1 = mn1;
    }
    float is0 = 1.0f / l0, is1 = 1.0f / l1;
    // stage output to smem, then coalesced store
    __syncthreads();
#pragma unroll
    for (int nf = 0; nf < 8; nf++) {
        int d0 = nf * 8 + 2 * ctg;
        int ml = mwb + gid;
        sO[d0 * 129 + ml]           = oacc[nf][0] * is0;
        sO[(d0 + 1) * 129 + ml]     = oacc[nf][1] * is0;
        sO[d0 * 129 + ml + 8]       = oacc[nf][2] * is1;
        sO[(d0 + 1) * 129 + ml + 8] = oacc[nf][3] * is1;
    }
    __syncthreads();
#pragma unroll
    for (int i = 0; i < 32; i++) {
        int e = t + i * 256;
        int d = e >> 7, m = e & 127;
        g_fgt[((size_t)b * Dd + d) * Nn + m0 + m] = sO[d * 129 + m];
    }
}

// ------------------- inter pre-bn: z2 = w_sem . fgt ------------------------
__global__ __launch_bounds__(128) void k_inter(const float* __restrict__ wsem) {
    __shared__ float sF[64][64];
    int b = blockIdx.y, n0 = blockIdx.x * 64, t = threadIdx.x;
    const float* fb = g_fgt + (size_t)b * Dd * Nn;
    for (int e = t; e < 4096; e += 128) {
        int d = e >> 6, nn = e & 63;
        sF[d][nn] = fb[(size_t)d * Nn + n0 + nn];
    }
    __syncthreads();
    float wr[64];
#pragma unroll
    for (int d = 0; d < 64; d++) wr[d] = wsem[t * 64 + d];
    float aS = 0.f, aQ = 0.f;
    for (int nn = 0; nn < 64; nn++) {
        float acc = 0.f;
#pragma unroll
        for (int d = 0; d < 64; d++) acc = fmaf(wr[d], sF[d][nn], acc);
        g_z2[((size_t)b * Nn + n0 + nn) * Oo + t] = acc;
        aS += acc;
        aQ = fmaf(acc, acc, aQ);
    }
    int blk = blockIdx.y * gridDim.x + blockIdx.x;
    g_p2s[(size_t)blk * Oo + t] = aS;
    g_p2q[(size_t)blk * Oo + t] = aQ;
}

// --------- bn stat finalize ------------------------------------------------
__global__ void k_bnstats(int which, int nblk, float invcnt,
                          const float* __restrict__ gamma, const float* __restrict__ beta) {
    int o = threadIdx.x;
    const float *ps, *pq;
    float *sc, *sh;
    if (which == 1) { ps = g_p1s; pq = g_p1q; sc = g_sc1; sh = g_sh1; }
    else if (which == 2) { ps = g_p2s; pq = g_p2q; sc = g_sc2; sh = g_sh2; }
    else { ps = g_p3s; pq = g_p3q; sc = g_sc3; sh = g_sh3; }
    float s = 0.f, q = 0.f;
    for (int i = 0; i < nblk; i++) {
        s += ps[(size_t)i * Oo + o];
        q += pq[(size_t)i * Oo + o];
    }
    float mean = s * invcnt;
    float var = q * invcnt - mean * mean;
    float scl = gamma[o] / sqrtf(var + 1e-5f);
    sc[o] = scl;
    sh[o] = beta[o] - mean * scl;
}

// --------- z3 = w_full . [lrelu(bn1(intra)); lrelu(bn2(inter))] ------------
__global__ __launch_bounds__(128) void k_z3(const float* __restrict__ wfull) {
    __shared__ float sC[16][256];
    __shared__ float sW[32][129];
    int bn0 = blockIdx.x * 16, t = threadIdx.x;
    for (int e = t; e < 16 * 256; e += 128) {
        int n = e >> 8, c = e & 255;
        int bn = bn0 + n;
        float pre;
        if (c < 128) {
            float s1 = g_sc1[c];
            float ym = (s1 >= 0.f) ? g_ymax[(size_t)bn * Oo + c] : g_ymin[(size_t)bn * Oo + c];
            pre = fmaf(s1, ym, g_sh1[c]);
        } else {
            int o = c - 128;
            pre = fmaf(g_sc2[o], g_z2[(size_t)bn * Oo + o], g_sh2[o]);
        }
        sC[n][c] = pre >= 0.f ? pre : NEG * pre;
    }
    float acc[16] = {};
    for (int ch = 0; ch < 8; ch++) {
        __syncthreads();
        for (int e = t; e < 32 * 128; e += 128) {
            int o = e >> 5, c = e & 31;
            sW[c][o] = wfull[(size_t)o * 256 + ch * 32 + c];
        }
        __syncthreads();
#pragma unroll 4
        for (int c = 0; c < 32; c++) {
            float w = sW[c][t];
            int cg = ch * 32 + c;
#pragma unroll
            for (int n = 0; n < 16; n++) acc[n] = fmaf(w, sC[n][cg], acc[n]);
        }
    }
    float aS = 0.f, aQ = 0.f;
#pragma unroll
    for (int n = 0; n < 16; n++) {
        float z = acc[n];
        g_z3[(size_t)(bn0 + n) * Oo + t] = z;
        aS += z;
        aQ = fmaf(z, z, aQ);
    }
    g_p3s[(size_t)blockIdx.x * Oo + t] = aS;
    g_p3q[(size_t)blockIdx.x * Oo + t] = aQ;
}

// --------- out[b,o,n] = lrelu(bn3(z3)) with transpose ----------------------
__global__ __launch_bounds__(256) void k_out(float* __restrict__ out) {
    __shared__ float tile[32][33];
    int b = blockIdx.z, o0 = blockIdx.y * 32, n0 = blockIdx.x * 32;
    int tx = threadIdx.x & 31, ty = threadIdx.x >> 5;
    float scl = g_sc3[o0 + tx], sh = g_sh3[o0 + tx];
#pragma unroll
    for (int i = 0; i < 4; i++) {
        int n = n0 + ty + i * 8;
        float v = fmaf(scl, g_z3[((size_t)b * Nn + n) * Oo + o0 + tx], sh);
        tile[ty + i * 8][tx] = v >= 0.f ? v : NEG * v;
    }
    __syncthreads();
#pragma unroll
    for (int i = 0; i < 4; i++) {
        int o = o0 + ty + i * 8;
        out[((size_t)b * Oo + o) * Nn + n0 + tx] = tile[tx][ty + i * 8];
    }
}

// ---------------------------------------------------------------------------
extern "C" void kernel_launch(void* const* d_in, const int* in_sizes, int n_in,
                              void* d_out, int out_size) {
    const float* f       = (const float*)d_in[0];
    const float* w_local = (const float*)d_in[1];
    const float* g_local = (const float*)d_in[2];
    const float* b_local = (const float*)d_in[3];
    const float* w_sem   = (const float*)d_in[4];
    const float* g_sem   = (const float*)d_in[5];
    const float* b_sem   = (const float*)d_in[6];
    const float* w_full  = (const float*)d_in[7];
    const float* g_full  = (const float*)d_in[8];
    const float* b_full  = (const float*)d_in[9];
    const float* wq = (const float*)d_in[10];
    const float* bq = (const float*)d_in[11];
    const float* wk = (const float*)d_in[12];
    const float* bk = (const float*)d_in[13];
    const float* wv = (const float*)d_in[14];
    const float* bv = (const float*)d_in[15];
    float* out = (float*)d_out;

    const int MM_SMEM = 128 * KST * 4;                 // 69632 bytes
    const int FL_SMEM = (64 + 128 + 64) * 72 * 4;      // 73728 bytes
    const int QK_SMEM = (64 * 65 + 192 * 64 + 192) * 4; // 66560 bytes
    cudaFuncSetAttribute(k_mm, cudaFuncAttributeMaxDynamicSharedMemorySize, MM_SMEM);
    cudaFuncSetAttribute(k_flash, cudaFuncAttributeMaxDynamicSharedMemorySize, FL_SMEM);
    cudaFuncSetAttribute(k_qkv, cudaFuncAttributeMaxDynamicSharedMemorySize, QK_SMEM);

    k_xx<<<64, 256>>>(f);
    k_tr<<<dim3(Nn / 32, Dd / 32, Bx), 256>>>(f);
    k_mm<<<dim3(32, 32, Bx), 256, MM_SMEM>>>(f);
    k_topk<<<Bx * Nn, 256>>>();
    k_projAB<<<Bx * Nn / 64, 256>>>(w_local);
    k_intra<<<Bx * Nn / 32, 128>>>(w_local);
    k_bnstats<<<1, 128>>>(1, 512, 1.0f / (Bx * Nn * Kk), g_local, b_local);
    k_qkv<<<dim3(64, Bx), 256, QK_SMEM>>>(f, wq, bq, wk, bk, wv, bv);
    k_flash<<<dim3(32, Bx), 256, FL_SMEM>>>();
    k_inter<<<dim3(64, Bx), 128>>>(w_sem);
    k_bnstats<<<1, 128>>>(2, 256, 1.0f / (Bx * Nn), g_sem, b_sem);
    k_z3<<<Bx * Nn / 16, 128>>>(w_full);
    k_bnstats<<<1, 128>>>(3, 1024, 1.0f / (Bx * Nn), g_full, b_full);
    k_out<<<dim3(Nn / 32, Oo / 32, Bx), 256>>>(out);
}